// round 13
// baseline (speedup 1.0000x reference)
#include <cuda_runtime.h>
#include <cuda_bf16.h>
#include <cstdint>

#define S_LEN 2048
#define DK 64
#define BH_N 32
#define SCALE 0.125f
#define PAD 72   // padded smem row stride (elems): 144B rows -> conflict-free ldmatrix

// ---------------- static device scratch (no allocations allowed) ----------------
__device__ float g_inv[BH_N * S_LEN];
__device__ uint2 g_mbits[BH_N * S_LEN * 32];          // 2-bit-per-col mask words
__device__ __nv_bfloat16 g_Qhi[BH_N * S_LEN * DK];
__device__ __nv_bfloat16 g_Qlo[BH_N * S_LEN * DK];
__device__ __nv_bfloat16 g_Khi[BH_N * S_LEN * DK];
__device__ __nv_bfloat16 g_Klo[BH_N * S_LEN * DK];
__device__ __nv_bfloat16 g_Vthi[BH_N * DK * S_LEN];   // [bh][d][s]
__device__ __nv_bfloat16 g_Vtlo[BH_N * DK * S_LEN];

// ---------------- helpers ----------------
__device__ __forceinline__ unsigned short bf_us(__nv_bfloat16 h) {
    return __bfloat16_as_ushort(h);
}
__device__ __forceinline__ void split2(float x, float y, uint32_t& hi, uint32_t& lo) {
    __nv_bfloat16 hx = __float2bfloat16(x), hy = __float2bfloat16(y);
    __nv_bfloat16 lx = __float2bfloat16(x - __bfloat162float(hx));
    __nv_bfloat16 ly = __float2bfloat16(y - __bfloat162float(hy));
    hi = (uint32_t)bf_us(hx) | ((uint32_t)bf_us(hy) << 16);
    lo = (uint32_t)bf_us(lx) | ((uint32_t)bf_us(ly) << 16);
}
// packed split: hi = bf16x2(x lo-half, y hi-half), lo = bf16x2 of residuals
__device__ __forceinline__ void split2p(float x, float y, uint32_t& hi, uint32_t& lo) {
    uint32_t h;
    asm("cvt.rn.satfinite.bf16x2.f32 %0, %1, %2;" : "=r"(h) : "f"(y), "f"(x));
    float fx = __uint_as_float(h << 16);
    float fy = __uint_as_float(h & 0xffff0000u);
    uint32_t l;
    asm("cvt.rn.satfinite.bf16x2.f32 %0, %1, %2;" : "=r"(l) : "f"(y - fy), "f"(x - fx));
    hi = h; lo = l;
}
__device__ __forceinline__ void mma_bf16(float* c, uint32_t a0, uint32_t a1,
                                         uint32_t a2, uint32_t a3,
                                         uint32_t b0, uint32_t b1) {
    asm volatile(
        "mma.sync.aligned.m16n8k16.row.col.f32.bf16.bf16.f32 "
        "{%0,%1,%2,%3}, {%4,%5,%6,%7}, {%8,%9}, {%0,%1,%2,%3};"
        : "+f"(c[0]), "+f"(c[1]), "+f"(c[2]), "+f"(c[3])
        : "r"(a0), "r"(a1), "r"(a2), "r"(a3), "r"(b0), "r"(b1));
}
__device__ __forceinline__ void lm4(uint32_t* r, uint32_t saddr) {
    asm volatile("ldmatrix.sync.aligned.m8n8.x4.shared.b16 {%0,%1,%2,%3}, [%4];"
                 : "=r"(r[0]), "=r"(r[1]), "=r"(r[2]), "=r"(r[3]) : "r"(saddr));
}
__device__ __forceinline__ void cp16u(uint32_t saddr, const void* g) {
    asm volatile("cp.async.cg.shared.global [%0], [%1], 16;" :: "r"(saddr), "l"(g));
}
#define CP_COMMIT() asm volatile("cp.async.commit_group;" ::: "memory")
#define CP_WAIT(n)  asm volatile("cp.async.wait_group %0;" :: "n"(n) : "memory")

// =======================================================================================
// K0a: Q,K fp32 -> bf16 hi/lo
// =======================================================================================
__global__ __launch_bounds__(256)
void convert_qk(const float* __restrict__ Q, const float* __restrict__ K)
{
    const size_t i = ((size_t)blockIdx.x * 256 + threadIdx.x) * 4;
    const float* src = blockIdx.y ? K : Q;
    __nv_bfloat16* hi = blockIdx.y ? g_Khi : g_Qhi;
    __nv_bfloat16* lo = blockIdx.y ? g_Klo : g_Qlo;
    float4 v = *(const float4*)(src + i);
    uint2 h, l;
    split2(v.x, v.y, h.x, l.x);
    split2(v.z, v.w, h.y, l.y);
    *(uint2*)(hi + i) = h;
    *(uint2*)(lo + i) = l;
}

// =======================================================================================
// K0b: V [bh][s][d] fp32 -> transposed Vt [bh][d][s] bf16 hi/lo
// =======================================================================================
__global__ __launch_bounds__(256)
void convert_v(const float* __restrict__ V)
{
    __shared__ float sm[64 * 65];
    const int bh = blockIdx.y;
    const int k0 = blockIdx.x * 64;
    const float* Vb = V + ((size_t)bh * S_LEN + k0) * DK;
    const int t = threadIdx.x;
#pragma unroll
    for (int i = 0; i < 4; ++i) {
        int idx = i * 256 + t;
        int row = idx >> 4, c4 = (idx & 15) * 4;
        float4 v = *(const float4*)(Vb + (size_t)row * DK + c4);
        sm[row * 65 + c4 + 0] = v.x; sm[row * 65 + c4 + 1] = v.y;
        sm[row * 65 + c4 + 2] = v.z; sm[row * 65 + c4 + 3] = v.w;
    }
    __syncthreads();
    const int d = t >> 2, qtr = t & 3;
    __nv_bfloat16* ph = g_Vthi + ((size_t)bh * DK + d) * S_LEN + k0 + qtr * 16;
    __nv_bfloat16* pl = g_Vtlo + ((size_t)bh * DK + d) * S_LEN + k0 + qtr * 16;
    uint32_t hw[8], lw[8];
#pragma unroll
    for (int j = 0; j < 8; ++j) {
        float a = sm[(qtr * 16 + 2 * j + 0) * 65 + d];
        float b = sm[(qtr * 16 + 2 * j + 1) * 65 + d];
        split2(a, b, hw[j], lw[j]);
    }
    *(uint4*)(ph + 0) = make_uint4(hw[0], hw[1], hw[2], hw[3]);
    *(uint4*)(ph + 8) = make_uint4(hw[4], hw[5], hw[6], hw[7]);
    *(uint4*)(pl + 0) = make_uint4(lw[0], lw[1], lw[2], lw[3]);
    *(uint4*)(pl + 8) = make_uint4(lw[4], lw[5], lw[6], lw[7]);
}

// =======================================================================================
// K0c: compact int32 mask -> 2 ballot words per (row, 64-col chunk).
// =======================================================================================
__global__ __launch_bounds__(256)
void mask_compact(const int* __restrict__ M)
{
    const int w = blockIdx.x * 8 + (threadIdx.x >> 5);
    const int lane = threadIdx.x & 31;
    const int chunk = w & 31;
    const int row = w >> 5;
    int2 m = *(const int2*)(M + (size_t)row * S_LEN + chunk * 64 + lane * 2);
    uint32_t be = __ballot_sync(0xffffffffu, m.x != 0);
    uint32_t bo = __ballot_sync(0xffffffffu, m.y != 0);
    if (lane == 0) g_mbits[(size_t)row * 32 + chunk] = make_uint2(be, bo);
}

// =======================================================================================
// Fused attention. 8 warps, warp tile 16(m) x 64(n), 32 k-chunks of 64.
// Q fragments hoisted to registers (loaded once via LDG). 3-stage cp.async pipeline,
// ONE barrier per chunk. ldmatrix B-fragments; bitmask epilogue with packed bf16x2
// split; P packed in registers for PV.
// smem: 3 stage buffers x 36864B, each = Kh@0, Kl@9216, Vh@18432, Vl@27648. 110592B.
// =======================================================================================
#define STG_B 36864
#define OF_KL 9216
#define OF_VH 18432
#define OF_VL 27648

__global__ __launch_bounds__(256, 2)
void attn_fused(float* __restrict__ E, float* __restrict__ C)
{
    extern __shared__ char smem[];
    const uint32_t sb = (uint32_t)__cvta_generic_to_shared(smem);

    const int t = threadIdx.x, wid = t >> 5, lane = t & 31;
    const int g = lane >> 2, tq = lane & 3;
    const int bh = blockIdx.y, q0 = blockIdx.x * 128;
    const int m0 = wid * 16;

    const __nv_bfloat16* Kp_h = g_Khi + ((size_t)bh * S_LEN) * DK;
    const __nv_bfloat16* Kp_l = g_Klo + ((size_t)bh * S_LEN) * DK;
    const __nv_bfloat16* Vp_h = g_Vthi + (size_t)bh * DK * S_LEN;
    const __nv_bfloat16* Vp_l = g_Vtlo + (size_t)bh * DK * S_LEN;

    // staging indices: thread covers rows sr0 (0..31) and sr1 (32..63)
    const int sr0 = t >> 3, sc0 = (t & 7) * 8;
    const int sr1 = (t + 256) >> 3, sc1 = ((t + 256) & 7) * 8;
    const uint32_t so0 = (uint32_t)(sr0 * PAD + sc0) * 2;
    const uint32_t so1 = (uint32_t)(sr1 * PAD + sc1) * 2;

#define STAGE(kn, base) do {                                                               \
        cp16u((base) + so0,         Kp_h + (size_t)((kn) + sr0) * DK + sc0);               \
        cp16u((base) + so1,         Kp_h + (size_t)((kn) + sr1) * DK + sc1);               \
        cp16u((base) + OF_KL + so0, Kp_l + (size_t)((kn) + sr0) * DK + sc0);               \
        cp16u((base) + OF_KL + so1, Kp_l + (size_t)((kn) + sr1) * DK + sc1);               \
        cp16u((base) + OF_VH + so0, Vp_h + (size_t)sr0 * S_LEN + (kn) + sc0);              \
        cp16u((base) + OF_VH + so1, Vp_h + (size_t)sr1 * S_LEN + (kn) + sc1);              \
        cp16u((base) + OF_VL + so0, Vp_l + (size_t)sr0 * S_LEN + (kn) + sc0);              \
        cp16u((base) + OF_VL + so1, Vp_l + (size_t)sr1 * S_LEN + (kn) + sc1);              \
    } while (0)

    // prologue: stage chunks 0 and 1
    STAGE(0, sb);
    CP_COMMIT();
    STAGE(64, sb + STG_B);
    CP_COMMIT();

    // hoist Q fragments to registers (A operand is invariant across all chunks)
    uint32_t aH[4][4], aL[4][4];
    {
        const __nv_bfloat16* qh = g_Qhi + ((size_t)bh * S_LEN + q0 + m0 + g) * DK;
        const __nv_bfloat16* ql = g_Qlo + ((size_t)bh * S_LEN + q0 + m0 + g) * DK;
#pragma unroll
        for (int ks = 0; ks < 4; ++ks) {
            const int cb = ks * 16 + 2 * tq;
            aH[ks][0] = *(const uint32_t*)(qh + cb);
            aH[ks][1] = *(const uint32_t*)(qh + 8 * DK + cb);
            aH[ks][2] = *(const uint32_t*)(qh + cb + 8);
            aH[ks][3] = *(const uint32_t*)(qh + 8 * DK + cb + 8);
            aL[ks][0] = *(const uint32_t*)(ql + cb);
            aL[ks][1] = *(const uint32_t*)(ql + 8 * DK + cb);
            aL[ks][2] = *(const uint32_t*)(ql + cb + 8);
            aL[ks][3] = *(const uint32_t*)(ql + 8 * DK + cb + 8);
        }
    }

    // B-fragment per-lane ldmatrix offset (within a 64xPAD tile)
    const int b_rowoff = (lane & 7) + ((lane >> 4) & 1) * 8;
    const int b_c8 = ((lane >> 3) & 1) * 8;
    const uint32_t boff = (uint32_t)(b_rowoff * PAD + b_c8) * 2;
#define BSTEP(ntp, ks) ((uint32_t)(ntp) * (16 * PAD * 2) + (uint32_t)(ks) * 32)

    float d[8][4];
#pragma unroll
    for (int nt = 0; nt < 8; ++nt)
#pragma unroll
        for (int j = 0; j < 4; ++j) d[nt][j] = 0.f;
    float rs0 = 0.f, rs1 = 0.f;

    float* Eb = E + ((size_t)bh * S_LEN + q0) * S_LEN;
    const uint2* mb0 = g_mbits + ((size_t)bh * S_LEN + q0 + m0 + g) * 32;
    const uint2* mb1 = g_mbits + ((size_t)bh * S_LEN + q0 + m0 + g + 8) * 32;

    uint32_t bCompute = sb, bNext = sb + STG_B, bStage = sb + 2 * STG_B;

    for (int kc = 0; kc < 32; ++kc) {
        if (kc < 31) CP_WAIT(1); else CP_WAIT(0);
        __syncthreads();   // staged data for bCompute visible; bStage free (read 2 iters ago)

        if (kc + 2 < 32) {
            STAGE((kc + 2) * 64, bStage);
            CP_COMMIT();
        }

        uint2 w0 = mb0[kc], w1 = mb1[kc];
        const uint32_t bKh = bCompute + boff;
        const uint32_t bKl = bCompute + OF_KL + boff;
        const uint32_t bVh = bCompute + OF_VH + boff;
        const uint32_t bVl = bCompute + OF_VL + boff;

        // ---- QK mma (A from registers) ----
        float c[8][4];
#pragma unroll
        for (int nt = 0; nt < 8; ++nt)
#pragma unroll
            for (int j = 0; j < 4; ++j) c[nt][j] = 0.f;

#pragma unroll
        for (int ks = 0; ks < 4; ++ks) {
#pragma unroll
            for (int ntp = 0; ntp < 4; ++ntp) {
                uint32_t bH[4], bL[4];
                lm4(bH, bKh + BSTEP(ntp, ks));
                lm4(bL, bKl + BSTEP(ntp, ks));
                mma_bf16(c[2 * ntp],     aH[ks][0], aH[ks][1], aH[ks][2], aH[ks][3], bH[0], bH[1]);
                mma_bf16(c[2 * ntp],     aH[ks][0], aH[ks][1], aH[ks][2], aH[ks][3], bL[0], bL[1]);
                mma_bf16(c[2 * ntp],     aL[ks][0], aL[ks][1], aL[ks][2], aL[ks][3], bH[0], bH[1]);
                mma_bf16(c[2 * ntp + 1], aH[ks][0], aH[ks][1], aH[ks][2], aH[ks][3], bH[2], bH[3]);
                mma_bf16(c[2 * ntp + 1], aH[ks][0], aH[ks][1], aH[ks][2], aH[ks][3], bL[2], bL[3]);
                mma_bf16(c[2 * ntp + 1], aL[ks][0], aL[ks][1], aL[ks][2], aL[ks][3], bH[2], bH[3]);
            }
        }

        // ---- epilogue: exp + bitmask + E store + row sums + packed P split ----
        uint32_t ph0[8], ph1[8], pl0[8], pl1[8];
#pragma unroll
        for (int nt = 0; nt < 8; ++nt) {
            const int pos = nt * 4 + tq;
            float e0 = ((w0.x >> pos) & 1u) ? 0.f : __expf(c[nt][0] * SCALE);
            float e1 = ((w0.y >> pos) & 1u) ? 0.f : __expf(c[nt][1] * SCALE);
            float e2 = ((w1.x >> pos) & 1u) ? 0.f : __expf(c[nt][2] * SCALE);
            float e3 = ((w1.y >> pos) & 1u) ? 0.f : __expf(c[nt][3] * SCALE);
            const size_t col = (size_t)kc * 64 + nt * 8 + 2 * tq;
            *(float2*)(Eb + (size_t)(m0 + g) * S_LEN + col)     = make_float2(e0, e1);
            *(float2*)(Eb + (size_t)(m0 + g + 8) * S_LEN + col) = make_float2(e2, e3);
            rs0 += e0 + e1;
            rs1 += e2 + e3;
            split2p(e0, e1, ph0[nt], pl0[nt]);
            split2p(e2, e3, ph1[nt], pl1[nt]);
        }

        // ---- PV mma: A = packed P (regs), B = Vt chunk (smem via ldmatrix) ----
#pragma unroll
        for (int ks = 0; ks < 4; ++ks) {
            uint32_t aH0 = ph0[2 * ks], aH1 = ph1[2 * ks], aH2 = ph0[2 * ks + 1], aH3 = ph1[2 * ks + 1];
            uint32_t aL0 = pl0[2 * ks], aL1 = pl1[2 * ks], aL2 = pl0[2 * ks + 1], aL3 = pl1[2 * ks + 1];
#pragma unroll
            for (int ntp = 0; ntp < 4; ++ntp) {
                uint32_t vH[4], vL[4];
                lm4(vH, bVh + BSTEP(ntp, ks));
                lm4(vL, bVl + BSTEP(ntp, ks));
                mma_bf16(d[2 * ntp],     aH0, aH1, aH2, aH3, vH[0], vH[1]);
                mma_bf16(d[2 * ntp],     aH0, aH1, aH2, aH3, vL[0], vL[1]);
                mma_bf16(d[2 * ntp],     aL0, aL1, aL2, aL3, vH[0], vH[1]);
                mma_bf16(d[2 * ntp + 1], aH0, aH1, aH2, aH3, vH[2], vH[3]);
                mma_bf16(d[2 * ntp + 1], aH0, aH1, aH2, aH3, vL[2], vL[3]);
                mma_bf16(d[2 * ntp + 1], aL0, aL1, aL2, aL3, vH[2], vH[3]);
            }
        }

        // rotate stage buffers
        uint32_t tmp = bCompute; bCompute = bNext; bNext = bStage; bStage = tmp;
    }

    // ---- final: row sums -> g_inv, context = acc * inv ----
    rs0 += __shfl_xor_sync(0xffffffffu, rs0, 1);
    rs0 += __shfl_xor_sync(0xffffffffu, rs0, 2);
    rs1 += __shfl_xor_sync(0xffffffffu, rs1, 1);
    rs1 += __shfl_xor_sync(0xffffffffu, rs1, 2);
    const float inv0 = 1.0f / rs0, inv1 = 1.0f / rs1;
    if (tq == 0) {
        g_inv[(size_t)bh * S_LEN + q0 + m0 + g]     = inv0;
        g_inv[(size_t)bh * S_LEN + q0 + m0 + g + 8] = inv1;
    }
    float* Cb = C + ((size_t)bh * S_LEN + q0) * DK;
#pragma unroll
    for (int nt = 0; nt < 8; ++nt) {
        const int dc = nt * 8 + 2 * tq;
        *(float2*)(Cb + (size_t)(m0 + g) * DK + dc) =
            make_float2(d[nt][0] * inv0, d[nt][1] * inv0);
        *(float2*)(Cb + (size_t)(m0 + g + 8) * DK + dc) =
            make_float2(d[nt][2] * inv1, d[nt][3] * inv1);
    }
#undef STAGE
#undef BSTEP
}

// =======================================================================================
// Normalize E in place: E[row][*] *= g_inv[row]. Pure stream.
// =======================================================================================
__global__ __launch_bounds__(256)
void norm_E(float* __restrict__ E)
{
    const size_t gidx = (size_t)blockIdx.x * 256 + threadIdx.x;   // float4 index
    const int row = (int)(gidx >> 9);                              // 512 float4 per row
    const float inv = g_inv[row];
    float4 v = *(const float4*)(E + gidx * 4);
    v.x *= inv; v.y *= inv; v.z *= inv; v.w *= inv;
    *(float4*)(E + gidx * 4) = v;
}

// =======================================================================================
extern "C" void kernel_launch(void* const* d_in, const int* in_sizes, int n_in,
                              void* d_out, int out_size)
{
    const float* Q = (const float*)d_in[0];
    const float* K = (const float*)d_in[1];
    const float* V = (const float*)d_in[2];
    const int*   M = (const int*)d_in[3];

    float* ctx = (float*)d_out;
    float* E   = ctx + (size_t)BH_N * S_LEN * DK;

    const int smem_f = 3 * STG_B;   // 110592
    cudaFuncSetAttribute(attn_fused, cudaFuncAttributeMaxDynamicSharedMemorySize, smem_f);

    convert_qk<<<dim3(4096, 2), 256>>>(Q, K);
    convert_v<<<dim3(32, BH_N), 256>>>(V);
    mask_compact<<<(BH_N * S_LEN * 32) / 8, 256>>>(M);
    attn_fused<<<dim3(16, BH_N), 256, smem_f>>>(E, ctx);
    norm_E<<<(int)(((size_t)BH_N * S_LEN * S_LEN / 4) / 256), 256>>>(E);
}

// round 14
// speedup vs baseline: 1.2014x; 1.2014x over previous
#include <cuda_runtime.h>
#include <cuda_fp16.h>
#include <cstdint>

#define S_LEN 2048
#define DK 64
#define BH_N 32
#define SCALE 0.125f
#define PAD 72   // padded smem row stride (elems): 144B rows -> conflict-free ldmatrix

// ---------------- static device scratch (no allocations allowed) ----------------
__device__ float g_inv[BH_N * S_LEN];
__device__ uint2 g_mbits[BH_N * S_LEN * 32];     // 2-bit-per-col mask words
__device__ __half g_Qhi[BH_N * S_LEN * DK];
__device__ __half g_Qlo[BH_N * S_LEN * DK];
__device__ __half g_K[BH_N * S_LEN * DK];        // plain fp16
__device__ __half g_Vt[BH_N * DK * S_LEN];       // [bh][d][s] plain fp16

// ---------------- helpers ----------------
// packed fp16 split: hi = f16x2(x, y), lo = f16x2 of residuals
__device__ __forceinline__ void split2h(float x, float y, uint32_t& hi, uint32_t& lo) {
    uint32_t h;
    asm("cvt.rn.f16x2.f32 %0, %1, %2;" : "=r"(h) : "f"(y), "f"(x));
    float fx = __half2float(__ushort_as_half((unsigned short)(h & 0xffffu)));
    float fy = __half2float(__ushort_as_half((unsigned short)(h >> 16)));
    uint32_t l;
    asm("cvt.rn.f16x2.f32 %0, %1, %2;" : "=r"(l) : "f"(y - fy), "f"(x - fx));
    hi = h; lo = l;
}
__device__ __forceinline__ void mma_fp16(float* c, uint32_t a0, uint32_t a1,
                                         uint32_t a2, uint32_t a3,
                                         uint32_t b0, uint32_t b1) {
    asm volatile(
        "mma.sync.aligned.m16n8k16.row.col.f32.f16.f16.f32 "
        "{%0,%1,%2,%3}, {%4,%5,%6,%7}, {%8,%9}, {%0,%1,%2,%3};"
        : "+f"(c[0]), "+f"(c[1]), "+f"(c[2]), "+f"(c[3])
        : "r"(a0), "r"(a1), "r"(a2), "r"(a3), "r"(b0), "r"(b1));
}
__device__ __forceinline__ void lm4(uint32_t* r, uint32_t saddr) {
    asm volatile("ldmatrix.sync.aligned.m8n8.x4.shared.b16 {%0,%1,%2,%3}, [%4];"
                 : "=r"(r[0]), "=r"(r[1]), "=r"(r[2]), "=r"(r[3]) : "r"(saddr));
}
__device__ __forceinline__ void cp16u(uint32_t saddr, const void* g) {
    asm volatile("cp.async.cg.shared.global [%0], [%1], 16;" :: "r"(saddr), "l"(g));
}
#define CP_COMMIT() asm volatile("cp.async.commit_group;" ::: "memory")
#define CP_WAIT(n)  asm volatile("cp.async.wait_group %0;" :: "n"(n) : "memory")

// =======================================================================================
// K0a: Q fp32 -> fp16 hi/lo (y=0);  K fp32 -> plain fp16 (y=1)
// =======================================================================================
__global__ __launch_bounds__(256)
void convert_qk(const float* __restrict__ Q, const float* __restrict__ K)
{
    const size_t i = ((size_t)blockIdx.x * 256 + threadIdx.x) * 4;
    if (blockIdx.y == 0) {
        float4 v = *(const float4*)(Q + i);
        uint2 h, l;
        split2h(v.x, v.y, h.x, l.x);
        split2h(v.z, v.w, h.y, l.y);
        *(uint2*)(g_Qhi + i) = h;
        *(uint2*)(g_Qlo + i) = l;
    } else {
        float4 v = *(const float4*)(K + i);
        __half2 a = __floats2half2_rn(v.x, v.y);
        __half2 b = __floats2half2_rn(v.z, v.w);
        *(uint2*)(g_K + i) = make_uint2(*(uint32_t*)&a, *(uint32_t*)&b);
    }
}

// =======================================================================================
// K0b: V [bh][s][d] fp32 -> transposed Vt [bh][d][s] plain fp16
// =======================================================================================
__global__ __launch_bounds__(256)
void convert_v(const float* __restrict__ V)
{
    __shared__ float sm[64 * 65];
    const int bh = blockIdx.y;
    const int k0 = blockIdx.x * 64;
    const float* Vb = V + ((size_t)bh * S_LEN + k0) * DK;
    const int t = threadIdx.x;
#pragma unroll
    for (int i = 0; i < 4; ++i) {
        int idx = i * 256 + t;
        int row = idx >> 4, c4 = (idx & 15) * 4;
        float4 v = *(const float4*)(Vb + (size_t)row * DK + c4);
        sm[row * 65 + c4 + 0] = v.x; sm[row * 65 + c4 + 1] = v.y;
        sm[row * 65 + c4 + 2] = v.z; sm[row * 65 + c4 + 3] = v.w;
    }
    __syncthreads();
    const int d = t >> 2, qtr = t & 3;
    __half* ph = g_Vt + ((size_t)bh * DK + d) * S_LEN + k0 + qtr * 16;
    uint32_t hw[8];
#pragma unroll
    for (int j = 0; j < 8; ++j) {
        float a = sm[(qtr * 16 + 2 * j + 0) * 65 + d];
        float b = sm[(qtr * 16 + 2 * j + 1) * 65 + d];
        __half2 p = __floats2half2_rn(a, b);
        hw[j] = *(uint32_t*)&p;
    }
    *(uint4*)(ph + 0) = make_uint4(hw[0], hw[1], hw[2], hw[3]);
    *(uint4*)(ph + 8) = make_uint4(hw[4], hw[5], hw[6], hw[7]);
}

// =======================================================================================
// K0c: compact int32 mask -> 2 ballot words per (row, 64-col chunk).
// =======================================================================================
__global__ __launch_bounds__(256)
void mask_compact(const int* __restrict__ M)
{
    const int w = blockIdx.x * 8 + (threadIdx.x >> 5);
    const int lane = threadIdx.x & 31;
    const int chunk = w & 31;
    const int row = w >> 5;
    int2 m = *(const int2*)(M + (size_t)row * S_LEN + chunk * 64 + lane * 2);
    uint32_t be = __ballot_sync(0xffffffffu, m.x != 0);
    uint32_t bo = __ballot_sync(0xffffffffu, m.y != 0);
    if (lane == 0) g_mbits[(size_t)row * 32 + chunk] = make_uint2(be, bo);
}

// =======================================================================================
// Fused attention. 8 warps, warp tile 16(m) x 64(n), 32 k-chunks of 64.
// fp16 2-product scheme: QK = (qh+ql)*k16, PV = (ph+pl)*v16. Q fragments hoisted.
// 3-stage cp.async pipeline, one barrier per chunk. Bitmask epilogue.
// smem: 3 stage buffers x 18432B, each = K@0 (64xPAD fp16), V@9216. Total 55296B.
// =======================================================================================
#define STG_B 18432
#define OF_V  9216

__global__ __launch_bounds__(256, 2)
void attn_fused(float* __restrict__ E, float* __restrict__ C)
{
    extern __shared__ char smem[];
    const uint32_t sb = (uint32_t)__cvta_generic_to_shared(smem);

    const int t = threadIdx.x, wid = t >> 5, lane = t & 31;
    const int g = lane >> 2, tq = lane & 3;
    const int bh = blockIdx.y, q0 = blockIdx.x * 128;
    const int m0 = wid * 16;

    const __half* Kp = g_K + (size_t)bh * S_LEN * DK;
    const __half* Vp = g_Vt + (size_t)bh * DK * S_LEN;

    // staging indices: thread covers rows sr0 (0..31) and sr1 (32..63)
    const int sr0 = t >> 3, sc0 = (t & 7) * 8;
    const int sr1 = (t + 256) >> 3, sc1 = ((t + 256) & 7) * 8;
    const uint32_t so0 = (uint32_t)(sr0 * PAD + sc0) * 2;
    const uint32_t so1 = (uint32_t)(sr1 * PAD + sc1) * 2;

#define STAGE(kn, base) do {                                                               \
        cp16u((base) + so0,        Kp + (size_t)((kn) + sr0) * DK + sc0);                  \
        cp16u((base) + so1,        Kp + (size_t)((kn) + sr1) * DK + sc1);                  \
        cp16u((base) + OF_V + so0, Vp + (size_t)sr0 * S_LEN + (kn) + sc0);                 \
        cp16u((base) + OF_V + so1, Vp + (size_t)sr1 * S_LEN + (kn) + sc1);                 \
    } while (0)

    STAGE(0, sb);
    CP_COMMIT();
    STAGE(64, sb + STG_B);
    CP_COMMIT();

    // hoist Q fragments (invariant A operand)
    uint32_t aH[4][4], aL[4][4];
    {
        const __half* qh = g_Qhi + ((size_t)bh * S_LEN + q0 + m0 + g) * DK;
        const __half* ql = g_Qlo + ((size_t)bh * S_LEN + q0 + m0 + g) * DK;
#pragma unroll
        for (int ks = 0; ks < 4; ++ks) {
            const int cb = ks * 16 + 2 * tq;
            aH[ks][0] = *(const uint32_t*)(qh + cb);
            aH[ks][1] = *(const uint32_t*)(qh + 8 * DK + cb);
            aH[ks][2] = *(const uint32_t*)(qh + cb + 8);
            aH[ks][3] = *(const uint32_t*)(qh + 8 * DK + cb + 8);
            aL[ks][0] = *(const uint32_t*)(ql + cb);
            aL[ks][1] = *(const uint32_t*)(ql + 8 * DK + cb);
            aL[ks][2] = *(const uint32_t*)(ql + cb + 8);
            aL[ks][3] = *(const uint32_t*)(ql + 8 * DK + cb + 8);
        }
    }

    // B-fragment per-lane ldmatrix offset (within a 64xPAD tile)
    const int b_rowoff = (lane & 7) + ((lane >> 4) & 1) * 8;
    const int b_c8 = ((lane >> 3) & 1) * 8;
    const uint32_t boff = (uint32_t)(b_rowoff * PAD + b_c8) * 2;
#define BSTEP(ntp, ks) ((uint32_t)(ntp) * (16 * PAD * 2) + (uint32_t)(ks) * 32)

    float d[8][4];
#pragma unroll
    for (int nt = 0; nt < 8; ++nt)
#pragma unroll
        for (int j = 0; j < 4; ++j) d[nt][j] = 0.f;
    float rs0 = 0.f, rs1 = 0.f;

    float* Eb = E + ((size_t)bh * S_LEN + q0) * S_LEN;
    const uint2* mb0 = g_mbits + ((size_t)bh * S_LEN + q0 + m0 + g) * 32;
    const uint2* mb1 = g_mbits + ((size_t)bh * S_LEN + q0 + m0 + g + 8) * 32;

    uint32_t bCompute = sb, bNext = sb + STG_B, bStage = sb + 2 * STG_B;

    for (int kc = 0; kc < 32; ++kc) {
        if (kc < 31) CP_WAIT(1); else CP_WAIT(0);
        __syncthreads();   // bCompute data visible; bStage free (read 2 iters ago)

        if (kc + 2 < 32) {
            STAGE((kc + 2) * 64, bStage);
            CP_COMMIT();
        }

        uint2 w0 = mb0[kc], w1 = mb1[kc];
        const uint32_t bK = bCompute + boff;
        const uint32_t bV = bCompute + OF_V + boff;

        // ---- QK mma: c += qh*k + ql*k ----
        float c[8][4];
#pragma unroll
        for (int nt = 0; nt < 8; ++nt)
#pragma unroll
            for (int j = 0; j < 4; ++j) c[nt][j] = 0.f;

#pragma unroll
        for (int ks = 0; ks < 4; ++ks) {
#pragma unroll
            for (int ntp = 0; ntp < 4; ++ntp) {
                uint32_t bH[4];
                lm4(bH, bK + BSTEP(ntp, ks));
                mma_fp16(c[2 * ntp],     aH[ks][0], aH[ks][1], aH[ks][2], aH[ks][3], bH[0], bH[1]);
                mma_fp16(c[2 * ntp],     aL[ks][0], aL[ks][1], aL[ks][2], aL[ks][3], bH[0], bH[1]);
                mma_fp16(c[2 * ntp + 1], aH[ks][0], aH[ks][1], aH[ks][2], aH[ks][3], bH[2], bH[3]);
                mma_fp16(c[2 * ntp + 1], aL[ks][0], aL[ks][1], aL[ks][2], aL[ks][3], bH[2], bH[3]);
            }
        }

        // ---- epilogue: exp + bitmask + E store + row sums + packed fp16 P split ----
        uint32_t ph0[8], ph1[8], pl0[8], pl1[8];
#pragma unroll
        for (int nt = 0; nt < 8; ++nt) {
            const int pos = nt * 4 + tq;
            float e0 = ((w0.x >> pos) & 1u) ? 0.f : __expf(c[nt][0] * SCALE);
            float e1 = ((w0.y >> pos) & 1u) ? 0.f : __expf(c[nt][1] * SCALE);
            float e2 = ((w1.x >> pos) & 1u) ? 0.f : __expf(c[nt][2] * SCALE);
            float e3 = ((w1.y >> pos) & 1u) ? 0.f : __expf(c[nt][3] * SCALE);
            const size_t col = (size_t)kc * 64 + nt * 8 + 2 * tq;
            *(float2*)(Eb + (size_t)(m0 + g) * S_LEN + col)     = make_float2(e0, e1);
            *(float2*)(Eb + (size_t)(m0 + g + 8) * S_LEN + col) = make_float2(e2, e3);
            rs0 += e0 + e1;
            rs1 += e2 + e3;
            split2h(e0, e1, ph0[nt], pl0[nt]);
            split2h(e2, e3, ph1[nt], pl1[nt]);
        }

        // ---- PV mma: d += ph*v + pl*v ----
#pragma unroll
        for (int ks = 0; ks < 4; ++ks) {
            uint32_t aH0 = ph0[2 * ks], aH1 = ph1[2 * ks], aH2 = ph0[2 * ks + 1], aH3 = ph1[2 * ks + 1];
            uint32_t aL0 = pl0[2 * ks], aL1 = pl1[2 * ks], aL2 = pl0[2 * ks + 1], aL3 = pl1[2 * ks + 1];
#pragma unroll
            for (int ntp = 0; ntp < 4; ++ntp) {
                uint32_t vH[4];
                lm4(vH, bV + BSTEP(ntp, ks));
                mma_fp16(d[2 * ntp],     aH0, aH1, aH2, aH3, vH[0], vH[1]);
                mma_fp16(d[2 * ntp],     aL0, aL1, aL2, aL3, vH[0], vH[1]);
                mma_fp16(d[2 * ntp + 1], aH0, aH1, aH2, aH3, vH[2], vH[3]);
                mma_fp16(d[2 * ntp + 1], aL0, aL1, aL2, aL3, vH[2], vH[3]);
            }
        }

        // rotate stage buffers
        uint32_t tmp = bCompute; bCompute = bNext; bNext = bStage; bStage = tmp;
    }

    // ---- final: row sums -> g_inv, context = acc * inv ----
    rs0 += __shfl_xor_sync(0xffffffffu, rs0, 1);
    rs0 += __shfl_xor_sync(0xffffffffu, rs0, 2);
    rs1 += __shfl_xor_sync(0xffffffffu, rs1, 1);
    rs1 += __shfl_xor_sync(0xffffffffu, rs1, 2);
    const float inv0 = 1.0f / rs0, inv1 = 1.0f / rs1;
    if (tq == 0) {
        g_inv[(size_t)bh * S_LEN + q0 + m0 + g]     = inv0;
        g_inv[(size_t)bh * S_LEN + q0 + m0 + g + 8] = inv1;
    }
    float* Cb = C + ((size_t)bh * S_LEN + q0) * DK;
#pragma unroll
    for (int nt = 0; nt < 8; ++nt) {
        const int dc = nt * 8 + 2 * tq;
        *(float2*)(Cb + (size_t)(m0 + g) * DK + dc) =
            make_float2(d[nt][0] * inv0, d[nt][1] * inv0);
        *(float2*)(Cb + (size_t)(m0 + g + 8) * DK + dc) =
            make_float2(d[nt][2] * inv1, d[nt][3] * inv1);
    }
#undef STAGE
#undef BSTEP
}

// =======================================================================================
// Normalize E in place: E[row][*] *= g_inv[row]. Pure stream.
// =======================================================================================
__global__ __launch_bounds__(256)
void norm_E(float* __restrict__ E)
{
    const size_t gidx = (size_t)blockIdx.x * 256 + threadIdx.x;   // float4 index
    const int row = (int)(gidx >> 9);                              // 512 float4 per row
    const float inv = g_inv[row];
    float4 v = *(const float4*)(E + gidx * 4);
    v.x *= inv; v.y *= inv; v.z *= inv; v.w *= inv;
    *(float4*)(E + gidx * 4) = v;
}

// =======================================================================================
extern "C" void kernel_launch(void* const* d_in, const int* in_sizes, int n_in,
                              void* d_out, int out_size)
{
    const float* Q = (const float*)d_in[0];
    const float* K = (const float*)d_in[1];
    const float* V = (const float*)d_in[2];
    const int*   M = (const int*)d_in[3];

    float* ctx = (float*)d_out;
    float* E   = ctx + (size_t)BH_N * S_LEN * DK;

    const int smem_f = 3 * STG_B;   // 55296
    cudaFuncSetAttribute(attn_fused, cudaFuncAttributeMaxDynamicSharedMemorySize, smem_f);

    convert_qk<<<dim3(4096, 2), 256>>>(Q, K);
    convert_v<<<dim3(32, BH_N), 256>>>(V);
    mask_compact<<<(BH_N * S_LEN * 32) / 8, 256>>>(M);
    attn_fused<<<dim3(16, BH_N), 256, smem_f>>>(E, ctx);
    norm_E<<<(int)(((size_t)BH_N * S_LEN * S_LEN / 4) / 256), 256>>>(E);
}